// round 15
// baseline (speedup 1.0000x reference)
#include <cuda_runtime.h>

// ---------------------------------------------------------------------------
// Tree3, round 15: 3-kernel pipeline.
//  K1: conv+sigmoid+pool, half-pair CTAs (grid 2048) -> 98.8% wave efficiency,
//      pool (fp32, pair-packed float2) to global scratch.
//  K2: tree einsum as GEMM per (gi, 16 pairs): tree_w staged once per 16 pairs.
//  K3: FC 336->10.
// ---------------------------------------------------------------------------

#define BTOT  2048
#define NPAIRS (BTOT/2)          // 1024

// K1 image staging: 18 rows per half, f2 row stride 34
#define IMG_ROW_F2 34
#define IMG_G_F2   (18*IMG_ROW_F2)     // 612

// pool scratch: [pair][45 ch][196] float2 (pair-packed)
__device__ float2 g_pool[NPAIRS * 45 * 196];
// tree outputs: [image][336]
__device__ float  g_t[BTOT * 336];

__device__ __forceinline__ float2 ffma2(float2 a, float2 b, float2 c) {
    unsigned long long au = *reinterpret_cast<unsigned long long*>(&a);
    unsigned long long bu = *reinterpret_cast<unsigned long long*>(&b);
    unsigned long long cu = *reinterpret_cast<unsigned long long*>(&c);
    unsigned long long du;
    asm("fma.rn.f32x2 %0, %1, %2, %3;" : "=l"(du) : "l"(au), "l"(bu), "l"(cu));
    return *reinterpret_cast<float2*>(&du);
}

__device__ __forceinline__ float sigmoidf_fast(float v) {
    return __fdividef(1.0f, 1.0f + __expf(-v));
}

// Full 14-column conv over an image pair (R14 proven body)
__device__ __forceinline__ void conv_task14(const float2* __restrict__ ib,
                                            const float*  __restrict__ wb,
                                            float2* __restrict__ pmax)
{
    float2 acc0[14], acc1[14];
    #pragma unroll
    for (int k = 0; k < 14; k++) {
        acc0[k] = make_float2(0.f, 0.f);
        acc1[k] = make_float2(0.f, 0.f);
    }

    float2 wpk[5];
    #pragma unroll
    for (int r = 0; r < 6; r++) {
        float2 P[18];
        const float4* rp = (const float4*)(ib + r * IMG_ROW_F2);
        #pragma unroll
        for (int u = 0; u < 9; u++) {
            float4 q = rp[u];
            P[2*u]   = make_float2(q.x, q.y);
            P[2*u+1] = make_float2(q.z, q.w);
        }
        if (r > 0) {
            #pragma unroll
            for (int kx = 0; kx < 5; kx++)
                #pragma unroll
                for (int ox = 0; ox < 14; ox++)
                    acc1[ox] = ffma2(P[ox + kx], wpk[kx], acc1[ox]);
        }
        if (r < 5) {
            #pragma unroll
            for (int kx = 0; kx < 5; kx++) {
                float w = wb[r * 5 + kx];
                wpk[kx] = make_float2(w, w);
            }
            #pragma unroll
            for (int kx = 0; kx < 5; kx++)
                #pragma unroll
                for (int ox = 0; ox < 14; ox++)
                    acc0[ox] = ffma2(P[ox + kx], wpk[kx], acc0[ox]);
        }
    }

    #pragma unroll
    for (int pj = 0; pj < 7; pj++) {
        float vx = fmaxf(fmaxf(acc0[2*pj].x, acc0[2*pj+1].x),
                         fmaxf(acc1[2*pj].x, acc1[2*pj+1].x));
        float vy = fmaxf(fmaxf(acc0[2*pj].y, acc0[2*pj+1].y),
                         fmaxf(acc1[2*pj].y, acc1[2*pj+1].y));
        pmax[pj] = make_float2(vx, vy);
    }
}

// ---------------- K1: conv + sigmoid + pool (half-pair CTAs) ----------------
// grid 2048: pair = bx>>1, ph = bx&1 (pi range ph*7 .. ph*7+6)
#define K1_SMEM_FLOATS (3*IMG_G_F2*2 + 1125 + 48)

__global__ __launch_bounds__(256, 2)
void tree3_conv(const float* __restrict__ x,
                const float* __restrict__ conv_w,
                const float* __restrict__ conv_b)
{
    extern __shared__ __align__(16) float sm[];
    float2* s_img = reinterpret_cast<float2*>(sm);     // [3][18][34]
    float*  s_w   = sm + 3*IMG_G_F2*2;
    float*  s_cb  = s_w + 1125;

    const int tid   = threadIdx.x;
    const int pair  = blockIdx.x >> 1;
    const int ph    = blockIdx.x & 1;
    const int rbase = ph * 14;
    const int b0    = pair * 2;

    for (int idx = tid; idx < 1125; idx += 256) s_w[idx] = conv_w[idx];
    if (tid < 45) s_cb[tid] = conv_b[tid];

    // stage 18 input rows of both images, pair-interleaved
    for (int idx = tid; idx < 3 * 18 * 8; idx += 256) {
        int grp = idx & 7;
        int row = (idx >> 3) % 18;
        int g   = idx / 144;
        const float* pA = x + (size_t)b0 * 3072 + g * 1024
                            + (rbase + row) * 32 + grp * 4;
        float4 a = *(const float4*)pA;
        float4 b = *(const float4*)(pA + 3072);
        float4* dst = (float4*)(s_img + g * IMG_G_F2 + row * IMG_ROW_F2 + grp * 4);
        dst[0] = make_float4(a.x, b.x, a.y, b.y);
        dst[1] = make_float4(a.z, b.z, a.w, b.w);
    }
    __syncthreads();

    // 630 tasks = (pil 0..6, half 0..1, c 0..44)
    for (int task = tid; task < 630; task += 256) {
        int c    = task % 45;
        int rest = task / 45;          // 0..13
        int half = rest & 1;
        int pil  = rest >> 1;          // 0..6
        int pi   = ph * 7 + pil;
        int g    = c / 15;

        const float*  wb = s_w + c * 25;
        const float2* ib = s_img + g * IMG_G_F2 + (2 * pil) * IMG_ROW_F2
                                 + half * 14;

        float2 pmax[7];
        conv_task14(ib, wb, pmax);

        float bias = s_cb[c];
        float2* pb = g_pool + (size_t)pair * (45*196) + c * 196
                            + pi * 14 + half * 7;
        #pragma unroll
        for (int pj = 0; pj < 7; pj++)
            pb[pj] = make_float2(sigmoidf_fast(pmax[pj].x + bias),
                                 sigmoidf_fast(pmax[pj].y + bias));
    }
}

// ---------------- K2: tree einsum GEMM per (gi, 16 pairs) ----------------
// grid 21*64 = 1344: gi = bx/64, pb = bx%64 (pairs pb*16 .. pb*16+15)
// smem: s_p [420 k][18 pad] f2 ; s_w2 [16 f][420 k] ; s_red [3][64][4] f2
#define SP_STRIDE 18
#define OFF_W2   (420*SP_STRIDE*2)            // floats: 15120
#define OFF_RED  (OFF_W2 + 16*420)            // 21840
#define K2_SMEM_FLOATS (OFF_RED + 3*64*4*2)   // 23376 floats = 93.5 KB

__global__ __launch_bounds__(256, 2)
void tree3_tree(const float* __restrict__ tree_w,
                const float* __restrict__ tree_b)
{
    extern __shared__ __align__(16) float sm[];
    float2* s_p   = reinterpret_cast<float2*>(sm);          // [420][18]
    float*  s_w2  = sm + OFF_W2;                            // [16][420]
    float2* s_red = reinterpret_cast<float2*>(sm + OFF_RED);// [3][64][4]

    const int tid = threadIdx.x;
    const int gi  = blockIdx.x / 64;
    const int pb  = blockIdx.x % 64;
    const int g   = gi / 7;
    const int i   = gi % 7;

    // stage tree_w slice: w[f][k], k = m*28 + j*4 + ki*2 + kj
    const float* twb = tree_w + g * 196 + i * 28;
    for (int idx = tid; idx < 16 * 420; idx += 256) {
        int f = idx / 420;
        int k = idx - f * 420;
        int m = k / 28;
        int r = k - m * 28;
        s_w2[f * 420 + k] = __ldg(twb + f * 8820 + m * 588 + r);
    }

    // stage pool slices: s_p[k][pr] for 16 pairs
    for (int idx = tid; idx < 16 * 420; idx += 256) {
        int pr = idx / 420;
        int e  = idx - pr * 420;
        int m  = e / 28;
        int e2 = e - m * 28;
        int ki = e2 / 14;
        int col = e2 - ki * 14;
        int j  = col >> 1;
        int kj = col & 1;
        int k  = m * 28 + (j << 2) + (ki << 1) + kj;
        float2 v = g_pool[(size_t)(pb * 16 + pr) * (45*196)
                          + (g * 15 + m) * 196 + (2 * i + ki) * 14 + col];
        s_p[k * SP_STRIDE + pr] = v;
    }
    __syncthreads();

    // compute: thread = (kq 0..3, f 0..15, prq 0..3); k-chunk 105
    const int kq   = tid >> 6;
    const int tile = tid & 63;
    const int f    = tile >> 2;
    const int prq  = tile & 3;
    const int k0   = kq * 105;

    const float*  wp = s_w2 + f * 420;
    const float4* p4 = reinterpret_cast<const float4*>(s_p);

    float2 acc[4];
    #pragma unroll
    for (int c = 0; c < 4; c++) acc[c] = make_float2(0.f, 0.f);

    #pragma unroll 5
    for (int k = k0; k < k0 + 105; k++) {
        float w = wp[k];
        float2 wv = make_float2(w, w);
        float4 a = p4[k * 9 + prq * 2];
        float4 b = p4[k * 9 + prq * 2 + 1];
        acc[0] = ffma2(make_float2(a.x, a.y), wv, acc[0]);
        acc[1] = ffma2(make_float2(a.z, a.w), wv, acc[1]);
        acc[2] = ffma2(make_float2(b.x, b.y), wv, acc[2]);
        acc[3] = ffma2(make_float2(b.z, b.w), wv, acc[3]);
    }

    // reduce the 4 k-chunks via smem
    if (kq > 0) {
        #pragma unroll
        for (int c = 0; c < 4; c++)
            s_red[((kq - 1) * 64 + tile) * 4 + c] = acc[c];
    }
    __syncthreads();
    if (kq == 0) {
        #pragma unroll
        for (int q = 0; q < 3; q++)
            #pragma unroll
            for (int c = 0; c < 4; c++) {
                float2 v = s_red[(q * 64 + tile) * 4 + c];
                acc[c].x += v.x; acc[c].y += v.y;
            }
        int tidx = f * 21 + gi;
        float tb = __ldg(tree_b + tidx);
        #pragma unroll
        for (int c = 0; c < 4; c++) {
            int pair = pb * 16 + prq * 4 + c;
            g_t[(pair * 2    ) * 336 + tidx] = sigmoidf_fast(acc[c].x + tb);
            g_t[(pair * 2 + 1) * 336 + tidx] = sigmoidf_fast(acc[c].y + tb);
        }
    }
}

// ---------------- K3: FC 336 -> 10 ----------------
__global__ __launch_bounds__(256)
void tree3_fc(const float* __restrict__ fc_w,
              const float* __restrict__ fc_b,
              float* __restrict__ out)
{
    int T = blockIdx.x * 256 + threadIdx.x;   // 80*256 = 20480 = 2048*10
    if (T >= BTOT * 10) return;
    int img = T / 10;
    int o   = T - img * 10;
    const float* tv = g_t + img * 336;
    const float* wv = fc_w + o * 336;
    float s = 0.f;
    #pragma unroll 4
    for (int k = 0; k < 336; k++)
        s = fmaf(tv[k], __ldg(wv + k), s);
    out[T] = s + fc_b[o];
}

extern "C" void kernel_launch(void* const* d_in, const int* in_sizes, int n_in,
                              void* d_out, int out_size)
{
    const float* x      = (const float*)d_in[0];
    const float* conv_w = (const float*)d_in[1];
    const float* conv_b = (const float*)d_in[2];
    const float* tree_w = (const float*)d_in[3];
    const float* tree_b = (const float*)d_in[4];
    const float* fc_w   = (const float*)d_in[5];
    const float* fc_b   = (const float*)d_in[6];
    float* out = (float*)d_out;

    const int smem1 = K1_SMEM_FLOATS * (int)sizeof(float);
    const int smem2 = K2_SMEM_FLOATS * (int)sizeof(float);
    cudaFuncSetAttribute(tree3_tree,
                         cudaFuncAttributeMaxDynamicSharedMemorySize, smem2);

    tree3_conv<<<BTOT, 256, smem1>>>(x, conv_w, conv_b);
    tree3_tree<<<21 * 64, 256, smem2>>>(tree_w, tree_b);
    tree3_fc<<<(BTOT * 10 + 255) / 256, 256>>>(fc_w, fc_b, out);
}

// round 16
// speedup vs baseline: 1.7313x; 1.7313x over previous
#include <cuda_runtime.h>

// ---------------------------------------------------------------------------
// Tree3 fused, round 16: R14 base, conv rebuilt with explicit double-buffered
// row prefetch (8/6 column subpasses so two row buffers fit in 128 regs).
// Phases 2 (tree einsum) and 3 (FC) identical to R14.
// ---------------------------------------------------------------------------

#define THREADS 256
#define BTOT 2048

// float2-unit strides
#define IMG_ROW_F2   34
#define IMG_PLANE_F2 1092
#define POOL_ROW_F2  15
#define POOL_CH_F2   211

#define SZ_IMG_F2    (3*IMG_PLANE_F2)
#define SZ_POOL_F2   (45*POOL_CH_F2)
#define OFF_POOL_F2  SZ_IMG_F2
#define OFF_W        (2*(SZ_IMG_F2 + SZ_POOL_F2))
#define OFF_CB       (OFF_W + 1128)
#define OFF_T        (OFF_CB + 48)
#define SMEM_FLOATS  (OFF_T + 2*336)

__device__ __forceinline__ float2 ffma2(float2 a, float2 b, float2 c) {
    unsigned long long au = *reinterpret_cast<unsigned long long*>(&a);
    unsigned long long bu = *reinterpret_cast<unsigned long long*>(&b);
    unsigned long long cu = *reinterpret_cast<unsigned long long*>(&c);
    unsigned long long du;
    asm("fma.rn.f32x2 %0, %1, %2, %3;" : "=l"(du) : "l"(au), "l"(bu), "l"(cu));
    return *reinterpret_cast<float2*>(&du);
}

__device__ __forceinline__ float sigmoidf_fast(float v) {
    return __fdividef(1.0f, 1.0f + __expf(-v));
}

// Column-subpass with explicit A/B row double-buffer: row r+1's loads are
// issued BEFORE row r's FFMA block, so LDS latency hides under compute.
template<int NC>
__device__ __forceinline__ void conv_subpass_pf(const float2* __restrict__ ib,
                                                const float*  __restrict__ wb,
                                                float2* __restrict__ pmax)
{
    constexpr int NF4 = (NC + 4) / 2;      // float4 loads per row window
    float2 acc0[NC], acc1[NC];
    #pragma unroll
    for (int k = 0; k < NC; k++) {
        acc0[k] = make_float2(0.f, 0.f);
        acc1[k] = make_float2(0.f, 0.f);
    }

    float4 A[NF4], B[NF4];
    {
        const float4* rp = (const float4*)ib;
        #pragma unroll
        for (int u = 0; u < NF4; u++) A[u] = rp[u];
    }

    float2 wpk[5];
    #pragma unroll
    for (int r = 0; r < 6; r++) {
        // prefetch next row into the inactive buffer
        if (r < 5) {
            const float4* rp = (const float4*)(ib + (r + 1) * IMG_ROW_F2);
            #pragma unroll
            for (int u = 0; u < NF4; u++) {
                if (r & 1) A[u] = rp[u];
                else       B[u] = rp[u];
            }
        }

        // unpack current row
        float2 P[2 * NF4];
        #pragma unroll
        for (int u = 0; u < NF4; u++) {
            float4 q = (r & 1) ? B[u] : A[u];
            P[2*u]   = make_float2(q.x, q.y);
            P[2*u+1] = make_float2(q.z, q.w);
        }

        if (r > 0) {
            #pragma unroll
            for (int kx = 0; kx < 5; kx++)
                #pragma unroll
                for (int ox = 0; ox < NC; ox++)
                    acc1[ox] = ffma2(P[ox + kx], wpk[kx], acc1[ox]);
        }
        if (r < 5) {
            #pragma unroll
            for (int kx = 0; kx < 5; kx++) {
                float w = wb[r * 5 + kx];
                wpk[kx] = make_float2(w, w);
            }
            #pragma unroll
            for (int kx = 0; kx < 5; kx++)
                #pragma unroll
                for (int ox = 0; ox < NC; ox++)
                    acc0[ox] = ffma2(P[ox + kx], wpk[kx], acc0[ox]);
        }
    }

    #pragma unroll
    for (int pj = 0; pj < NC / 2; pj++) {
        float vx = fmaxf(fmaxf(acc0[2*pj].x, acc0[2*pj+1].x),
                         fmaxf(acc1[2*pj].x, acc1[2*pj+1].x));
        float vy = fmaxf(fmaxf(acc0[2*pj].y, acc0[2*pj+1].y),
                         fmaxf(acc1[2*pj].y, acc1[2*pj+1].y));
        pmax[pj] = make_float2(vx, vy);
    }
}

__global__ __launch_bounds__(THREADS, 2)
void tree3_fused(const float* __restrict__ x,
                 const float* __restrict__ conv_w,
                 const float* __restrict__ conv_b,
                 const float* __restrict__ tree_w,
                 const float* __restrict__ tree_b,
                 const float* __restrict__ fc_w,
                 const float* __restrict__ fc_b,
                 float* __restrict__ out)
{
    extern __shared__ __align__(16) float sm[];
    float2* s_img  = reinterpret_cast<float2*>(sm);
    float2* s_pool = reinterpret_cast<float2*>(sm) + OFF_POOL_F2;
    float*  s_w    = sm + OFF_W;
    float*  s_cb   = sm + OFF_CB;
    float*  s_t    = sm + OFF_T;

    const int tid  = threadIdx.x;
    const int lane = tid & 31;
    const int wid  = tid >> 5;
    const int b0   = blockIdx.x * 2;

    // ---- stage conv weights + bias ----
    for (int idx = tid; idx < 1125; idx += THREADS) s_w[idx] = conv_w[idx];
    if (tid < 45) s_cb[tid] = conv_b[tid];

    // ---- stage the image pair, interleaved (float4 in/out) ----
    for (int idx = tid; idx < 3 * 32 * 8; idx += THREADS) {
        int grp = idx & 7;
        int row = (idx >> 3) & 31;
        int gch = idx >> 8;
        const float* pA = x + (size_t)b0 * 3072 + gch * 1024 + row * 32 + grp * 4;
        float4 a = *(const float4*)pA;
        float4 b = *(const float4*)(pA + 3072);
        float4* dst = (float4*)(s_img + gch * IMG_PLANE_F2
                                      + row * IMG_ROW_F2 + grp * 4);
        dst[0] = make_float4(a.x, b.x, a.y, b.y);
        dst[1] = make_float4(a.z, b.z, a.w, b.w);
    }
    __syncthreads();

    // ---- phase 1: packed conv + sigmoid(max-pool), prefetched subpasses ----
    for (int task = tid; task < 45 * 28; task += THREADS) {
        int c    = task % 45;
        int rest = task / 45;
        int half = rest & 1;
        int pi   = rest >> 1;

        int g  = c / 15;
        const float*  wb = s_w + c * 25;
        const float2* ib = s_img + g * IMG_PLANE_F2
                                 + (pi * 2) * IMG_ROW_F2 + half * 14;

        float2 pmax[7];
        conv_subpass_pf<8>(ib,     wb, pmax);
        conv_subpass_pf<6>(ib + 8, wb, pmax + 4);

        float bias = s_cb[c];
        float2* pb = s_pool + c * POOL_CH_F2 + pi * POOL_ROW_F2 + half * 7;
        #pragma unroll
        for (int pj = 0; pj < 7; pj++)
            pb[pj] = make_float2(sigmoidf_fast(pmax[pj].x + bias),
                                 sigmoidf_fast(pmax[pj].y + bias));
    }
    __syncthreads();

    // ---- phase 2: tree einsum, one warp per gi, lanes = (j,ki,kj) ----
    {
        const bool act = lane < 28;
        const int jr  = lane >> 2;
        const int j   = (jr > 6) ? 6 : jr;
        const int ki  = (lane >> 1) & 1;
        const int kj  = lane & 1;

        for (int gi = wid; gi < 21; gi += THREADS / 32) {
            int g = gi / 7;
            int i = gi % 7;

            const float* wl = tree_w + g * 196 + i * 28 + j * 4 + ki * 2 + kj;
            const float2* pl = s_pool + (g * 15) * POOL_CH_F2
                             + (2 * i + ki) * POOL_ROW_F2 + 2 * j + kj;

            float2 acc[16];
            #pragma unroll
            for (int f = 0; f < 16; f++) acc[f] = make_float2(0.f, 0.f);

            float2 pv = pl[0];
            #pragma unroll
            for (int m = 0; m < 15; m++) {
                float2 pv_next = (m < 14) ? pl[(m + 1) * POOL_CH_F2] : pv;
                #pragma unroll
                for (int f = 0; f < 16; f++) {
                    float w = act ? __ldg(wl + m * 588 + f * 8820) : 0.f;
                    acc[f] = ffma2(pv, make_float2(w, w), acc[f]);
                }
                pv = pv_next;
            }

            // select-butterfly reduction (R11 form)
            {
                bool b = (lane & 16) != 0;
                #pragma unroll
                for (int f = 0; f < 8; f++) {
                    float2 snd = b ? acc[f] : acc[f + 8];
                    float rx = __shfl_xor_sync(0xffffffffu, snd.x, 16);
                    float ry = __shfl_xor_sync(0xffffffffu, snd.y, 16);
                    float2 kp = b ? acc[f + 8] : acc[f];
                    acc[f] = make_float2(kp.x + rx, kp.y + ry);
                }
            }
            {
                bool b = (lane & 8) != 0;
                #pragma unroll
                for (int f = 0; f < 4; f++) {
                    float2 snd = b ? acc[f] : acc[f + 4];
                    float rx = __shfl_xor_sync(0xffffffffu, snd.x, 8);
                    float ry = __shfl_xor_sync(0xffffffffu, snd.y, 8);
                    float2 kp = b ? acc[f + 4] : acc[f];
                    acc[f] = make_float2(kp.x + rx, kp.y + ry);
                }
            }
            {
                bool b = (lane & 4) != 0;
                #pragma unroll
                for (int f = 0; f < 2; f++) {
                    float2 snd = b ? acc[f] : acc[f + 2];
                    float rx = __shfl_xor_sync(0xffffffffu, snd.x, 4);
                    float ry = __shfl_xor_sync(0xffffffffu, snd.y, 4);
                    float2 kp = b ? acc[f + 2] : acc[f];
                    acc[f] = make_float2(kp.x + rx, kp.y + ry);
                }
            }
            {
                bool b = (lane & 2) != 0;
                float2 snd = b ? acc[0] : acc[1];
                float rx = __shfl_xor_sync(0xffffffffu, snd.x, 2);
                float ry = __shfl_xor_sync(0xffffffffu, snd.y, 2);
                float2 kp = b ? acc[1] : acc[0];
                acc[0] = make_float2(kp.x + rx, kp.y + ry);
            }
            acc[0].x += __shfl_xor_sync(0xffffffffu, acc[0].x, 1);
            acc[0].y += __shfl_xor_sync(0xffffffffu, acc[0].y, 1);

            int f   = (lane >> 1) & 15;
            int idx = f * 21 + gi;
            float tb = tree_b[idx];
            if ((lane & 1) == 0)
                s_t[      idx] = sigmoidf_fast(acc[0].x + tb);
            else
                s_t[336 + idx] = sigmoidf_fast(acc[0].y + tb);
        }
    }
    __syncthreads();

    // ---- phase 3: FC 336 -> 10 ----
    if (tid < 160) {
        int part  = tid & 7;
        int combo = tid >> 3;
        int img   = combo / 10;
        int o     = combo % 10;
        const float* tv = s_t + img * 336;
        const float* wv = fc_w + o * 336;
        float s = 0.f;
        for (int k = part; k < 336; k += 8)
            s = fmaf(tv[k], wv[k], s);
        s += __shfl_xor_sync(0xffffffffu, s, 1);
        s += __shfl_xor_sync(0xffffffffu, s, 2);
        s += __shfl_xor_sync(0xffffffffu, s, 4);
        if (part == 0)
            out[(b0 + img) * 10 + o] = s + fc_b[o];
    }
}

extern "C" void kernel_launch(void* const* d_in, const int* in_sizes, int n_in,
                              void* d_out, int out_size)
{
    const float* x      = (const float*)d_in[0];
    const float* conv_w = (const float*)d_in[1];
    const float* conv_b = (const float*)d_in[2];
    const float* tree_w = (const float*)d_in[3];
    const float* tree_b = (const float*)d_in[4];
    const float* fc_w   = (const float*)d_in[5];
    const float* fc_b   = (const float*)d_in[6];
    float* out = (float*)d_out;

    const int smem_bytes = SMEM_FLOATS * (int)sizeof(float);
    cudaFuncSetAttribute(tree3_fused,
                         cudaFuncAttributeMaxDynamicSharedMemorySize, smem_bytes);

    tree3_fused<<<BTOT / 2, THREADS, smem_bytes>>>(
        x, conv_w, conv_b, tree_w, tree_b, fc_w, fc_b, out);
}